// round 13
// baseline (speedup 1.0000x reference)
#include <cuda_runtime.h>
#include <cuda_fp16.h>
#include <math.h>
#include <stdint.h>

#define MAX_N 50000
#define MAX_E 800000
#define D 128
#define C 40
#define NB 64

// ---------------- static scratch ----------------
__device__ int   g_cnt[MAX_N];
__device__ int   g_degc[MAX_N];
__device__ int   g_rowptr[MAX_N + 1];
__device__ int   g_off[MAX_N];
__device__ int   g_bagg[NB];
__device__ int   g_bflag[NB];
__device__ int2  g_cse[MAX_E];        // packed CSR: {src, weight_bits}
__device__ float g_dinv[MAX_N];
// fp16 feature buffers (uint4 for 16B alignment)
__device__ uint4 g_x16_[MAX_N * D / 8];
__device__ uint4 g_tx1h_[MAX_N * D / 8];
__device__ uint4 g_tx2h_[MAX_N * D / 8];
__device__ uint4 g_hh_[MAX_N * D / 8];
// W^T fp16: w1t [128n][384k], w2t [40n][384k]
__device__ uint4 g_w1t_[128 * 384 / 8];
__device__ uint4 g_w2t_[40 * 384 / 8];

// ---------------- graph prep ----------------
__global__ void k_zero(int n) {
    int i = blockIdx.x * blockDim.x + threadIdx.x;
    if (i < n) { g_cnt[i] = 0; g_degc[i] = 0; }
    if (i < NB) { g_bflag[i] = 0; g_bagg[i] = 0; }
}

__global__ void k_count(const int* __restrict__ ei, int E) {
    int e = blockIdx.x * blockDim.x + threadIdx.x;
    if (e < E) {
        atomicAdd(&g_degc[ei[e]], 1);
        atomicAdd(&g_cnt[ei[E + e]], 1);
    }
}

// fused: dinv (grid-stride) + single-pass scan with parallel predecessor wait.
__global__ void k_scanf(int n, int nb) {
    int b = blockIdx.x, t = threadIdx.x;

    for (int i = b * 256 + t; i < n; i += nb * 256) {
        int d = g_degc[i];
        g_dinv[i] = (d > 0) ? rsqrtf((float)d) : 0.0f;
    }

    int base = b * 1024 + t * 4;
    int v[4];
    int s = 0;
#pragma unroll
    for (int j = 0; j < 4; ++j) {
        int i = base + j;
        v[j] = (i < n) ? g_cnt[i] : 0;
        s += v[j];
    }
    int inc = s;
#pragma unroll
    for (int o = 1; o < 32; o <<= 1) {
        int u = __shfl_up_sync(0xffffffffu, inc, o);
        if ((t & 31) >= o) inc += u;
    }
    __shared__ int ws[8];
    __shared__ int wo[8];
    __shared__ int stot;
    __shared__ int sbase;
    __shared__ int preds[NB];
    if ((t & 31) == 31) ws[t >> 5] = inc;
    __syncthreads();
    if (t == 0) {
        int p = 0;
#pragma unroll
        for (int w = 0; w < 8; ++w) { wo[w] = p; p += ws[w]; }
        stot = p;
        atomicExch(&g_bagg[b], p);
        __threadfence();
        atomicExch(&g_bflag[b], 1);
    }
    __syncthreads();

    if (t < b) {
        while (atomicAdd(&g_bflag[t], 0) == 0) { }
        preds[t] = atomicAdd(&g_bagg[t], 0);
    }
    __syncthreads();
    if (t == 0) {
        int acc = 0;
        for (int p = 0; p < b; ++p) acc += preds[p];
        sbase = acc;
        if (b == nb - 1) g_rowptr[n] = acc + stot;
    }
    __syncthreads();

    int pre = sbase + wo[t >> 5] + (inc - s);
#pragma unroll
    for (int j = 0; j < 4; ++j) {
        int i = base + j;
        if (i < n) { g_rowptr[i] = pre; g_off[i] = pre; }
        pre += v[j];
    }
}

__global__ void k_scatter(const int* __restrict__ ei, int E) {
    int e = blockIdx.x * blockDim.x + threadIdx.x;
    if (e < E) {
        int s = ei[e];
        int t = ei[E + e];
        int p = atomicAdd(&g_off[t], 1);
        float w = -g_dinv[s] * g_dinv[t];
        g_cse[p] = make_int2(s, __float_as_int(w));
    }
}

// ---------------- fused convert: x->fp16, W1^T->fp16, W2^T->fp16 (R11-proven) ----------------
__global__ void k_conv(const float* __restrict__ x, const float* __restrict__ W1,
                       const float* __restrict__ W2, int n4) {
    int i = blockIdx.x * blockDim.x + threadIdx.x;
    if (i < n4) {
        float4 v = ((const float4*)x)[i];
        __half2 h0 = __floats2half2_rn(v.x, v.y);
        __half2 h1 = __floats2half2_rn(v.z, v.w);
        uint2 o;
        o.x = *(uint32_t*)&h0;
        o.y = *(uint32_t*)&h1;
        *(uint2*)((__half*)g_x16_ + (size_t)i * 4) = o;
    }
    if (i < 128 * 384) {
        int n = i / 384;
        int r = i % 384;
        int term = r >> 7;
        int k = r & 127;
        ((__half*)g_w1t_)[i] = __float2half(W1[(size_t)term * D * D + (size_t)k * D + n]);
    }
    if (i < C * 384) {
        int n = i / 384;
        int r = i % 384;
        int term = r >> 7;
        int k = r & 127;
        ((__half*)g_w2t_)[i] = __float2half(W2[(size_t)term * D * C + (size_t)k * C + n]);
    }
}

// ---------------- SpMV: CSR gather, 2 edges/iter split-warp, packed int2 ----------------
__global__ void k_spmv_h(const __half* __restrict__ hin, __half* __restrict__ hout,
                         const __half* __restrict__ sub, float scale, int n) {
    int node = blockIdx.x * (blockDim.x >> 5) + (threadIdx.x >> 5);
    int lane = threadIdx.x & 31;
    int half = lane >> 4;
    int hl = lane & 15;
    if (node >= n) return;
    int beg = g_rowptr[node];
    int end = g_rowptr[node + 1];
    float acc[8];
#pragma unroll
    for (int q = 0; q < 8; ++q) acc[q] = 0.0f;

    for (int j = beg; j < end; j += 2) {
        int jj = j + half;
        if (jj < end) {
            int2 sw = __ldg(&g_cse[jj]);
            int s = sw.x;
            float w = __int_as_float(sw.y);
            uint4 u = *(const uint4*)(hin + (size_t)s * D + hl * 8);
            float2 f0 = __half22float2(*(__half2*)&u.x);
            float2 f1 = __half22float2(*(__half2*)&u.y);
            float2 f2 = __half22float2(*(__half2*)&u.z);
            float2 f3 = __half22float2(*(__half2*)&u.w);
            acc[0] += w * f0.x; acc[1] += w * f0.y;
            acc[2] += w * f1.x; acc[3] += w * f1.y;
            acc[4] += w * f2.x; acc[5] += w * f2.y;
            acc[6] += w * f3.x; acc[7] += w * f3.y;
        }
    }
#pragma unroll
    for (int q = 0; q < 8; ++q)
        acc[q] += __shfl_xor_sync(0xffffffffu, acc[q], 16);

    if (half == 0) {
        float r[8];
        if (sub) {
            uint4 u = *(const uint4*)(sub + (size_t)node * D + hl * 8);
            float2 f0 = __half22float2(*(__half2*)&u.x);
            float2 f1 = __half22float2(*(__half2*)&u.y);
            float2 f2 = __half22float2(*(__half2*)&u.z);
            float2 f3 = __half22float2(*(__half2*)&u.w);
            r[0] = scale * acc[0] - f0.x; r[1] = scale * acc[1] - f0.y;
            r[2] = scale * acc[2] - f1.x; r[3] = scale * acc[3] - f1.y;
            r[4] = scale * acc[4] - f2.x; r[5] = scale * acc[5] - f2.y;
            r[6] = scale * acc[6] - f3.x; r[7] = scale * acc[7] - f3.y;
        } else {
#pragma unroll
            for (int q = 0; q < 8; ++q) r[q] = acc[q];
        }
        __half2 h0 = __floats2half2_rn(r[0], r[1]);
        __half2 h1 = __floats2half2_rn(r[2], r[3]);
        __half2 h2 = __floats2half2_rn(r[4], r[5]);
        __half2 h3 = __floats2half2_rn(r[6], r[7]);
        uint4 o;
        o.x = *(uint32_t*)&h0; o.y = *(uint32_t*)&h1;
        o.z = *(uint32_t*)&h2; o.w = *(uint32_t*)&h3;
        *(uint4*)(hout + (size_t)node * D + hl * 8) = o;
    }
}

// ---------------- layer-1 GEMM: fp16 mma (R11-proven) ----------------
#define S1 40

__global__ void k_gemm1h(const float* __restrict__ b1, int n) {
    __shared__ __half As1[128 * S1];
    __shared__ __half Bs1[128 * S1];
    __shared__ float bsh[128];

    int tid = threadIdx.x;
    int wid = tid >> 5, lane = tid & 31;
    int wm = wid >> 1;
    int wn = wid & 1;
    int g = lane >> 2, tq = lane & 3;
    int row0 = blockIdx.x * 128;

    if (tid < 128) bsh[tid] = b1[tid];

    __half* hh = (__half*)g_hh_;
    const __half* w1t = (const __half*)g_w1t_;

    float c[2][8][4];
#pragma unroll
    for (int mt = 0; mt < 2; ++mt)
#pragma unroll
        for (int nt = 0; nt < 8; ++nt)
#pragma unroll
            for (int q = 0; q < 4; ++q) c[mt][nt][q] = 0.0f;

    for (int ch = 0; ch < 12; ++ch) {
        int term = ch >> 2;
        int coff = (ch & 3) * 32;
        const __half* A = (term == 0) ? (const __half*)g_x16_
                        : (term == 1) ? (const __half*)g_tx1h_
                                      : (const __half*)g_tx2h_;

#pragma unroll
        for (int q = 0; q < 2; ++q) {
            int idx = tid + q * 256;
            int r = idx >> 2;
            int c8 = (idx & 3) * 8;
            int grow = row0 + r;
            uint4 v = (grow < n)
                ? *(const uint4*)(A + (size_t)grow * D + coff + c8)
                : make_uint4(0u, 0u, 0u, 0u);
            *(uint4*)&As1[r * S1 + c8] = v;
        }
#pragma unroll
        for (int q = 0; q < 2; ++q) {
            int idx = tid + q * 256;
            int r = idx >> 2;
            int c8 = (idx & 3) * 8;
            *(uint4*)&Bs1[r * S1 + c8] =
                *(const uint4*)(w1t + (size_t)r * 384 + term * 128 + coff + c8);
        }
        __syncthreads();

#pragma unroll
        for (int ks = 0; ks < 2; ++ks) {
            int kb = ks * 16;
            uint32_t a[2][4];
#pragma unroll
            for (int mt = 0; mt < 2; ++mt) {
                const __half* ar = &As1[(wm * 32 + mt * 16 + g) * S1 + kb + 2 * tq];
                a[mt][0] = *(const uint32_t*)ar;
                a[mt][1] = *(const uint32_t*)(ar + 8 * S1);
                a[mt][2] = *(const uint32_t*)(ar + 8);
                a[mt][3] = *(const uint32_t*)(ar + 8 * S1 + 8);
            }
#pragma unroll
            for (int nt = 0; nt < 8; ++nt) {
                const __half* br = &Bs1[(wn * 64 + nt * 8 + g) * S1 + kb + 2 * tq];
                uint32_t b0 = *(const uint32_t*)br;
                uint32_t b1r = *(const uint32_t*)(br + 8);
#pragma unroll
                for (int mt = 0; mt < 2; ++mt) {
                    asm volatile(
                        "mma.sync.aligned.m16n8k16.row.col.f32.f16.f16.f32 "
                        "{%0,%1,%2,%3}, {%4,%5,%6,%7}, {%8,%9}, {%0,%1,%2,%3};\n"
                        : "+f"(c[mt][nt][0]), "+f"(c[mt][nt][1]),
                          "+f"(c[mt][nt][2]), "+f"(c[mt][nt][3])
                        : "r"(a[mt][0]), "r"(a[mt][1]), "r"(a[mt][2]), "r"(a[mt][3]),
                          "r"(b0), "r"(b1r));
                }
            }
        }
        __syncthreads();
    }

#pragma unroll
    for (int mt = 0; mt < 2; ++mt) {
#pragma unroll
        for (int nt = 0; nt < 8; ++nt) {
            int col = wn * 64 + nt * 8 + 2 * tq;
            float bb0 = bsh[col], bb1 = bsh[col + 1];
            int r0 = row0 + wm * 32 + mt * 16 + g;
            if (r0 < n) {
                __half2 v0 = __floats2half2_rn(fmaxf(c[mt][nt][0] + bb0, 0.f),
                                               fmaxf(c[mt][nt][1] + bb1, 0.f));
                *(__half2*)(hh + (size_t)r0 * D + col) = v0;
            }
            int r1 = r0 + 8;
            if (r1 < n) {
                __half2 v1 = __floats2half2_rn(fmaxf(c[mt][nt][2] + bb0, 0.f),
                                               fmaxf(c[mt][nt][3] + bb1, 0.f));
                *(__half2*)(hh + (size_t)r1 * D + col) = v1;
            }
        }
    }
}

// ---------------- layer-2 GEMM: fp16 mma + fused log_softmax (R7/R10-proven) ----------------
#define S2 40

__global__ void k_gemm2(const float* __restrict__ b2, float* __restrict__ out, int n) {
    __shared__ __half As2[128 * S2];
    __shared__ __half Bs2[40 * S2];
    __shared__ float bsh[40];

    int tid = threadIdx.x;
    int wid = tid >> 5, lane = tid & 31;
    int g = lane >> 2, tq = lane & 3;
    int row0 = blockIdx.x * 128;

    if (tid < 40) bsh[tid] = b2[tid];

    const __half* w2t = (const __half*)g_w2t_;

    float c[5][4];
#pragma unroll
    for (int nt = 0; nt < 5; ++nt)
#pragma unroll
        for (int q = 0; q < 4; ++q) c[nt][q] = 0.0f;

    for (int ch = 0; ch < 12; ++ch) {
        int term = ch >> 2;
        int coff = (ch & 3) * 32;
        const __half* A = (term == 0) ? (const __half*)g_hh_
                        : (term == 1) ? (const __half*)g_tx1h_
                                      : (const __half*)g_tx2h_;

#pragma unroll
        for (int q = 0; q < 2; ++q) {
            int idx = tid + q * 256;
            int r = idx >> 2;
            int c8 = (idx & 3) * 8;
            int grow = row0 + r;
            uint4 v = (grow < n)
                ? *(const uint4*)(A + (size_t)grow * D + coff + c8)
                : make_uint4(0u, 0u, 0u, 0u);
            *(uint4*)&As2[r * S2 + c8] = v;
        }
        if (tid < 160) {
            int r = tid >> 2;
            int c8 = (tid & 3) * 8;
            *(uint4*)&Bs2[r * S2 + c8] =
                *(const uint4*)(w2t + (size_t)r * 384 + term * 128 + coff + c8);
        }
        __syncthreads();

#pragma unroll
        for (int ks = 0; ks < 2; ++ks) {
            int kb = ks * 16;
            const __half* ar = &As2[(wid * 16 + g) * S2 + kb + 2 * tq];
            uint32_t a0 = *(const uint32_t*)ar;
            uint32_t a1 = *(const uint32_t*)(ar + 8 * S2);
            uint32_t a2 = *(const uint32_t*)(ar + 8);
            uint32_t a3 = *(const uint32_t*)(ar + 8 * S2 + 8);
#pragma unroll
            for (int nt = 0; nt < 5; ++nt) {
                const __half* br = &Bs2[(nt * 8 + g) * S2 + kb + 2 * tq];
                uint32_t b0 = *(const uint32_t*)br;
                uint32_t b1r = *(const uint32_t*)(br + 8);
                asm volatile(
                    "mma.sync.aligned.m16n8k16.row.col.f32.f16.f16.f32 "
                    "{%0,%1,%2,%3}, {%4,%5,%6,%7}, {%8,%9}, {%0,%1,%2,%3};\n"
                    : "+f"(c[nt][0]), "+f"(c[nt][1]), "+f"(c[nt][2]), "+f"(c[nt][3])
                    : "r"(a0), "r"(a1), "r"(a2), "r"(a3), "r"(b0), "r"(b1r));
            }
        }
        __syncthreads();
    }

    float zz[5][4];
#pragma unroll
    for (int nt = 0; nt < 5; ++nt) {
        float bb0 = bsh[nt * 8 + 2 * tq];
        float bb1 = bsh[nt * 8 + 2 * tq + 1];
        zz[nt][0] = c[nt][0] + bb0;
        zz[nt][1] = c[nt][1] + bb1;
        zz[nt][2] = c[nt][2] + bb0;
        zz[nt][3] = c[nt][3] + bb1;
    }
    float m0 = -INFINITY, m1 = -INFINITY;
#pragma unroll
    for (int nt = 0; nt < 5; ++nt) {
        m0 = fmaxf(m0, fmaxf(zz[nt][0], zz[nt][1]));
        m1 = fmaxf(m1, fmaxf(zz[nt][2], zz[nt][3]));
    }
    m0 = fmaxf(m0, __shfl_xor_sync(0xffffffffu, m0, 1));
    m0 = fmaxf(m0, __shfl_xor_sync(0xffffffffu, m0, 2));
    m1 = fmaxf(m1, __shfl_xor_sync(0xffffffffu, m1, 1));
    m1 = fmaxf(m1, __shfl_xor_sync(0xffffffffu, m1, 2));
    float s0 = 0.0f, s1 = 0.0f;
#pragma unroll
    for (int nt = 0; nt < 5; ++nt) {
        s0 += __expf(zz[nt][0] - m0) + __expf(zz[nt][1] - m0);
        s1 += __expf(zz[nt][2] - m1) + __expf(zz[nt][3] - m1);
    }
    s0 += __shfl_xor_sync(0xffffffffu, s0, 1);
    s0 += __shfl_xor_sync(0xffffffffu, s0, 2);
    s1 += __shfl_xor_sync(0xffffffffu, s1, 1);
    s1 += __shfl_xor_sync(0xffffffffu, s1, 2);
    float lse0 = m0 + logf(s0);
    float lse1 = m1 + logf(s1);

    int r0 = row0 + wid * 16 + g;
    int r1 = r0 + 8;
#pragma unroll
    for (int nt = 0; nt < 5; ++nt) {
        int col = nt * 8 + 2 * tq;
        if (r0 < n)
            *(float2*)(out + (size_t)r0 * C + col) =
                make_float2(zz[nt][0] - lse0, zz[nt][1] - lse0);
        if (r1 < n)
            *(float2*)(out + (size_t)r1 * C + col) =
                make_float2(zz[nt][2] - lse1, zz[nt][3] - lse1);
    }
}

static void* sym_addr(const void* sym) {
    void* p = nullptr;
    cudaGetSymbolAddress(&p, sym);
    return p;
}

extern "C" void kernel_launch(void* const* d_in, const int* in_sizes, int n_in,
                              void* d_out, int out_size) {
    const float* x  = (const float*)d_in[0];
    const int*   ei = (const int*)d_in[1];
    const float* W1 = (const float*)d_in[2];
    const float* b1 = (const float*)d_in[3];
    const float* W2 = (const float*)d_in[4];
    const float* b2 = (const float*)d_in[5];
    float*       out = (float*)d_out;

    int N = in_sizes[0] / D;
    int E = in_sizes[1] / 2;
    int n4 = N * D / 4;

    __half* x16  = (__half*)sym_addr((const void*)g_x16_);
    __half* tx1h = (__half*)sym_addr((const void*)g_tx1h_);
    __half* tx2h = (__half*)sym_addr((const void*)g_tx2h_);
    __half* hh   = (__half*)sym_addr((const void*)g_hh_);

    dim3 b256(256);
    int gN  = (N + 255) / 256;
    int gE  = (E + 255) / 256;
    int gN4 = (n4 + 255) / 256;
    int gSp = (N * 32 + 255) / 256;
    int gG  = (N + 127) / 128;
    int nb  = (N + 1023) / 1024;

    // graph prep: 5 launches (R11 structure + int2 scatter)
    k_zero<<<gN, b256>>>(N);
    k_count<<<gE, b256>>>(ei, E);
    k_scanf<<<nb, b256>>>(N, nb);
    k_scatter<<<gE, b256>>>(ei, E);
    k_conv<<<gN4, b256>>>(x, W1, W2, n4);

    // layer 1
    k_spmv_h<<<gSp, b256>>>(x16,  tx1h, nullptr, 1.0f, N);
    k_spmv_h<<<gSp, b256>>>(tx1h, tx2h, x16,     2.0f, N);
    k_gemm1h<<<gG, b256>>>(b1, N);

    // layer 2
    k_spmv_h<<<gSp, b256>>>(hh,   tx1h, nullptr, 1.0f, N);
    k_spmv_h<<<gSp, b256>>>(tx1h, tx2h, hh,      2.0f, N);
    k_gemm2<<<gG, b256>>>(b2, out, N);
}

// round 14
// speedup vs baseline: 1.0635x; 1.0635x over previous
#include <cuda_runtime.h>
#include <cuda_fp16.h>
#include <math.h>
#include <stdint.h>

#define MAX_N 50000
#define MAX_E 800000
#define D 128
#define C 40
#define NB 64

// ---------------- static scratch ----------------
// NOTE: g_cnt/g_degc/g_bflag/g_bagg are zero at module load and re-zeroed at the
// END of every kernel_launch (tail of k_gemm2), so each call sees them zeroed.
__device__ int   g_cnt[MAX_N];
__device__ int   g_degc[MAX_N];
__device__ int   g_rowptr[MAX_N + 1];
__device__ int   g_off[MAX_N];
__device__ int   g_bagg[NB];
__device__ int   g_bflag[NB];
__device__ int   g_csrc[MAX_E];
__device__ float g_csw[MAX_E];
__device__ float g_dinv[MAX_N];
// fp16 feature buffers (uint4 for 16B alignment)
__device__ uint4 g_x16_[MAX_N * D / 8];
__device__ uint4 g_tx1h_[MAX_N * D / 8];
__device__ uint4 g_tx2h_[MAX_N * D / 8];
__device__ uint4 g_hh_[MAX_N * D / 8];
// W^T fp16: w1t [128n][384k], w2t [40n][384k]
__device__ uint4 g_w1t_[128 * 384 / 8];
__device__ uint4 g_w2t_[40 * 384 / 8];

// ---------------- graph prep ----------------
__global__ void k_count(const int* __restrict__ ei, int E) {
    int e = blockIdx.x * blockDim.x + threadIdx.x;
    if (e < E) {
        atomicAdd(&g_degc[ei[e]], 1);
        atomicAdd(&g_cnt[ei[E + e]], 1);
    }
}

// fused: dinv (grid-stride) + single-pass scan with parallel predecessor wait.
__global__ void k_scanf(int n, int nb) {
    int b = blockIdx.x, t = threadIdx.x;

    for (int i = b * 256 + t; i < n; i += nb * 256) {
        int d = g_degc[i];
        g_dinv[i] = (d > 0) ? rsqrtf((float)d) : 0.0f;
    }

    int base = b * 1024 + t * 4;
    int v[4];
    int s = 0;
#pragma unroll
    for (int j = 0; j < 4; ++j) {
        int i = base + j;
        v[j] = (i < n) ? g_cnt[i] : 0;
        s += v[j];
    }
    int inc = s;
#pragma unroll
    for (int o = 1; o < 32; o <<= 1) {
        int u = __shfl_up_sync(0xffffffffu, inc, o);
        if ((t & 31) >= o) inc += u;
    }
    __shared__ int ws[8];
    __shared__ int wo[8];
    __shared__ int stot;
    __shared__ int sbase;
    __shared__ int preds[NB];
    if ((t & 31) == 31) ws[t >> 5] = inc;
    __syncthreads();
    if (t == 0) {
        int p = 0;
#pragma unroll
        for (int w = 0; w < 8; ++w) { wo[w] = p; p += ws[w]; }
        stot = p;
        atomicExch(&g_bagg[b], p);
        __threadfence();
        atomicExch(&g_bflag[b], 1);
    }
    __syncthreads();

    if (t < b) {
        while (atomicAdd(&g_bflag[t], 0) == 0) { }
        preds[t] = atomicAdd(&g_bagg[t], 0);
    }
    __syncthreads();
    if (t == 0) {
        int acc = 0;
        for (int p = 0; p < b; ++p) acc += preds[p];
        sbase = acc;
        if (b == nb - 1) g_rowptr[n] = acc + stot;
    }
    __syncthreads();

    int pre = sbase + wo[t >> 5] + (inc - s);
#pragma unroll
    for (int j = 0; j < 4; ++j) {
        int i = base + j;
        if (i < n) { g_rowptr[i] = pre; g_off[i] = pre; }
        pre += v[j];
    }
}

__global__ void k_scatter(const int* __restrict__ ei, int E) {
    int e = blockIdx.x * blockDim.x + threadIdx.x;
    if (e < E) {
        int s = ei[e];
        int t = ei[E + e];
        int p = atomicAdd(&g_off[t], 1);
        g_csrc[p] = s;
        g_csw[p] = -g_dinv[s] * g_dinv[t];
    }
}

// ---------------- fused convert: x->fp16, W1^T->fp16, W2^T->fp16 ----------------
__global__ void k_conv(const float* __restrict__ x, const float* __restrict__ W1,
                       const float* __restrict__ W2, int n4) {
    int i = blockIdx.x * blockDim.x + threadIdx.x;
    if (i < n4) {
        float4 v = ((const float4*)x)[i];
        __half2 h0 = __floats2half2_rn(v.x, v.y);
        __half2 h1 = __floats2half2_rn(v.z, v.w);
        uint2 o;
        o.x = *(uint32_t*)&h0;
        o.y = *(uint32_t*)&h1;
        *(uint2*)((__half*)g_x16_ + (size_t)i * 4) = o;
    }
    if (i < 128 * 384) {
        int n = i / 384;
        int r = i % 384;
        int term = r >> 7;
        int k = r & 127;
        ((__half*)g_w1t_)[i] = __float2half(W1[(size_t)term * D * D + (size_t)k * D + n]);
    }
    if (i < C * 384) {
        int n = i / 384;
        int r = i % 384;
        int term = r >> 7;
        int k = r & 127;
        ((__half*)g_w2t_)[i] = __float2half(W2[(size_t)term * D * C + (size_t)k * C + n]);
    }
}

// ---------------- SpMV: CSR gather, 2 edges/iter split-warp (R11-proven) ----------------
__global__ void k_spmv_h(const __half* __restrict__ hin, __half* __restrict__ hout,
                         const __half* __restrict__ sub, float scale, int n) {
    int node = blockIdx.x * (blockDim.x >> 5) + (threadIdx.x >> 5);
    int lane = threadIdx.x & 31;
    int half = lane >> 4;
    int hl = lane & 15;
    if (node >= n) return;
    int beg = g_rowptr[node];
    int end = g_rowptr[node + 1];
    float acc[8];
#pragma unroll
    for (int q = 0; q < 8; ++q) acc[q] = 0.0f;

    for (int j = beg; j < end; j += 2) {
        int jj = j + half;
        if (jj < end) {
            int s = __ldg(&g_csrc[jj]);
            float w = __ldg(&g_csw[jj]);
            uint4 u = *(const uint4*)(hin + (size_t)s * D + hl * 8);
            float2 f0 = __half22float2(*(__half2*)&u.x);
            float2 f1 = __half22float2(*(__half2*)&u.y);
            float2 f2 = __half22float2(*(__half2*)&u.z);
            float2 f3 = __half22float2(*(__half2*)&u.w);
            acc[0] += w * f0.x; acc[1] += w * f0.y;
            acc[2] += w * f1.x; acc[3] += w * f1.y;
            acc[4] += w * f2.x; acc[5] += w * f2.y;
            acc[6] += w * f3.x; acc[7] += w * f3.y;
        }
    }
#pragma unroll
    for (int q = 0; q < 8; ++q)
        acc[q] += __shfl_xor_sync(0xffffffffu, acc[q], 16);

    if (half == 0) {
        float r[8];
        if (sub) {
            uint4 u = *(const uint4*)(sub + (size_t)node * D + hl * 8);
            float2 f0 = __half22float2(*(__half2*)&u.x);
            float2 f1 = __half22float2(*(__half2*)&u.y);
            float2 f2 = __half22float2(*(__half2*)&u.z);
            float2 f3 = __half22float2(*(__half2*)&u.w);
            r[0] = scale * acc[0] - f0.x; r[1] = scale * acc[1] - f0.y;
            r[2] = scale * acc[2] - f1.x; r[3] = scale * acc[3] - f1.y;
            r[4] = scale * acc[4] - f2.x; r[5] = scale * acc[5] - f2.y;
            r[6] = scale * acc[6] - f3.x; r[7] = scale * acc[7] - f3.y;
        } else {
#pragma unroll
            for (int q = 0; q < 8; ++q) r[q] = acc[q];
        }
        __half2 h0 = __floats2half2_rn(r[0], r[1]);
        __half2 h1 = __floats2half2_rn(r[2], r[3]);
        __half2 h2 = __floats2half2_rn(r[4], r[5]);
        __half2 h3 = __floats2half2_rn(r[6], r[7]);
        uint4 o;
        o.x = *(uint32_t*)&h0; o.y = *(uint32_t*)&h1;
        o.z = *(uint32_t*)&h2; o.w = *(uint32_t*)&h3;
        *(uint4*)(hout + (size_t)node * D + hl * 8) = o;
    }
}

// ---------------- layer-1 GEMM: fp16 mma (R11-proven) ----------------
#define S1 40

__global__ void k_gemm1h(const float* __restrict__ b1, int n) {
    __shared__ __half As1[128 * S1];
    __shared__ __half Bs1[128 * S1];
    __shared__ float bsh[128];

    int tid = threadIdx.x;
    int wid = tid >> 5, lane = tid & 31;
    int wm = wid >> 1;
    int wn = wid & 1;
    int g = lane >> 2, tq = lane & 3;
    int row0 = blockIdx.x * 128;

    if (tid < 128) bsh[tid] = b1[tid];

    __half* hh = (__half*)g_hh_;
    const __half* w1t = (const __half*)g_w1t_;

    float c[2][8][4];
#pragma unroll
    for (int mt = 0; mt < 2; ++mt)
#pragma unroll
        for (int nt = 0; nt < 8; ++nt)
#pragma unroll
            for (int q = 0; q < 4; ++q) c[mt][nt][q] = 0.0f;

    for (int ch = 0; ch < 12; ++ch) {
        int term = ch >> 2;
        int coff = (ch & 3) * 32;
        const __half* A = (term == 0) ? (const __half*)g_x16_
                        : (term == 1) ? (const __half*)g_tx1h_
                                      : (const __half*)g_tx2h_;

#pragma unroll
        for (int q = 0; q < 2; ++q) {
            int idx = tid + q * 256;
            int r = idx >> 2;
            int c8 = (idx & 3) * 8;
            int grow = row0 + r;
            uint4 v = (grow < n)
                ? *(const uint4*)(A + (size_t)grow * D + coff + c8)
                : make_uint4(0u, 0u, 0u, 0u);
            *(uint4*)&As1[r * S1 + c8] = v;
        }
#pragma unroll
        for (int q = 0; q < 2; ++q) {
            int idx = tid + q * 256;
            int r = idx >> 2;
            int c8 = (idx & 3) * 8;
            *(uint4*)&Bs1[r * S1 + c8] =
                *(const uint4*)(w1t + (size_t)r * 384 + term * 128 + coff + c8);
        }
        __syncthreads();

#pragma unroll
        for (int ks = 0; ks < 2; ++ks) {
            int kb = ks * 16;
            uint32_t a[2][4];
#pragma unroll
            for (int mt = 0; mt < 2; ++mt) {
                const __half* ar = &As1[(wm * 32 + mt * 16 + g) * S1 + kb + 2 * tq];
                a[mt][0] = *(const uint32_t*)ar;
                a[mt][1] = *(const uint32_t*)(ar + 8 * S1);
                a[mt][2] = *(const uint32_t*)(ar + 8);
                a[mt][3] = *(const uint32_t*)(ar + 8 * S1 + 8);
            }
#pragma unroll
            for (int nt = 0; nt < 8; ++nt) {
                const __half* br = &Bs1[(wn * 64 + nt * 8 + g) * S1 + kb + 2 * tq];
                uint32_t b0 = *(const uint32_t*)br;
                uint32_t b1r = *(const uint32_t*)(br + 8);
#pragma unroll
                for (int mt = 0; mt < 2; ++mt) {
                    asm volatile(
                        "mma.sync.aligned.m16n8k16.row.col.f32.f16.f16.f32 "
                        "{%0,%1,%2,%3}, {%4,%5,%6,%7}, {%8,%9}, {%0,%1,%2,%3};\n"
                        : "+f"(c[mt][nt][0]), "+f"(c[mt][nt][1]),
                          "+f"(c[mt][nt][2]), "+f"(c[mt][nt][3])
                        : "r"(a[mt][0]), "r"(a[mt][1]), "r"(a[mt][2]), "r"(a[mt][3]),
                          "r"(b0), "r"(b1r));
                }
            }
        }
        __syncthreads();
    }

#pragma unroll
    for (int mt = 0; mt < 2; ++mt) {
#pragma unroll
        for (int nt = 0; nt < 8; ++nt) {
            int col = wn * 64 + nt * 8 + 2 * tq;
            float bb0 = bsh[col], bb1 = bsh[col + 1];
            int r0 = row0 + wm * 32 + mt * 16 + g;
            if (r0 < n) {
                __half2 v0 = __floats2half2_rn(fmaxf(c[mt][nt][0] + bb0, 0.f),
                                               fmaxf(c[mt][nt][1] + bb1, 0.f));
                *(__half2*)(hh + (size_t)r0 * D + col) = v0;
            }
            int r1 = r0 + 8;
            if (r1 < n) {
                __half2 v1 = __floats2half2_rn(fmaxf(c[mt][nt][2] + bb0, 0.f),
                                               fmaxf(c[mt][nt][3] + bb1, 0.f));
                *(__half2*)(hh + (size_t)r1 * D + col) = v1;
            }
        }
    }
}

// ---------------- layer-2 GEMM: fp16 mma + fused log_softmax + state re-zero ----------------
#define S2 40

__global__ void k_gemm2(const float* __restrict__ b2, float* __restrict__ out, int n) {
    __shared__ __half As2[128 * S2];
    __shared__ __half Bs2[40 * S2];
    __shared__ float bsh[40];

    int tid = threadIdx.x;
    int wid = tid >> 5, lane = tid & 31;
    int g = lane >> 2, tq = lane & 3;
    int row0 = blockIdx.x * 128;

    if (tid < 40) bsh[tid] = b2[tid];

    const __half* w2t = (const __half*)g_w2t_;

    float c[5][4];
#pragma unroll
    for (int nt = 0; nt < 5; ++nt)
#pragma unroll
        for (int q = 0; q < 4; ++q) c[nt][q] = 0.0f;

    for (int ch = 0; ch < 12; ++ch) {
        int term = ch >> 2;
        int coff = (ch & 3) * 32;
        const __half* A = (term == 0) ? (const __half*)g_hh_
                        : (term == 1) ? (const __half*)g_tx1h_
                                      : (const __half*)g_tx2h_;

#pragma unroll
        for (int q = 0; q < 2; ++q) {
            int idx = tid + q * 256;
            int r = idx >> 2;
            int c8 = (idx & 3) * 8;
            int grow = row0 + r;
            uint4 v = (grow < n)
                ? *(const uint4*)(A + (size_t)grow * D + coff + c8)
                : make_uint4(0u, 0u, 0u, 0u);
            *(uint4*)&As2[r * S2 + c8] = v;
        }
        if (tid < 160) {
            int r = tid >> 2;
            int c8 = (tid & 3) * 8;
            *(uint4*)&Bs2[r * S2 + c8] =
                *(const uint4*)(w2t + (size_t)r * 384 + term * 128 + coff + c8);
        }
        __syncthreads();

#pragma unroll
        for (int ks = 0; ks < 2; ++ks) {
            int kb = ks * 16;
            const __half* ar = &As2[(wid * 16 + g) * S2 + kb + 2 * tq];
            uint32_t a0 = *(const uint32_t*)ar;
            uint32_t a1 = *(const uint32_t*)(ar + 8 * S2);
            uint32_t a2 = *(const uint32_t*)(ar + 8);
            uint32_t a3 = *(const uint32_t*)(ar + 8 * S2 + 8);
#pragma unroll
            for (int nt = 0; nt < 5; ++nt) {
                const __half* br = &Bs2[(nt * 8 + g) * S2 + kb + 2 * tq];
                uint32_t b0 = *(const uint32_t*)br;
                uint32_t b1r = *(const uint32_t*)(br + 8);
                asm volatile(
                    "mma.sync.aligned.m16n8k16.row.col.f32.f16.f16.f32 "
                    "{%0,%1,%2,%3}, {%4,%5,%6,%7}, {%8,%9}, {%0,%1,%2,%3};\n"
                    : "+f"(c[nt][0]), "+f"(c[nt][1]), "+f"(c[nt][2]), "+f"(c[nt][3])
                    : "r"(a0), "r"(a1), "r"(a2), "r"(a3), "r"(b0), "r"(b1r));
            }
        }
        __syncthreads();
    }

    float zz[5][4];
#pragma unroll
    for (int nt = 0; nt < 5; ++nt) {
        float bb0 = bsh[nt * 8 + 2 * tq];
        float bb1 = bsh[nt * 8 + 2 * tq + 1];
        zz[nt][0] = c[nt][0] + bb0;
        zz[nt][1] = c[nt][1] + bb1;
        zz[nt][2] = c[nt][2] + bb0;
        zz[nt][3] = c[nt][3] + bb1;
    }
    float m0 = -INFINITY, m1 = -INFINITY;
#pragma unroll
    for (int nt = 0; nt < 5; ++nt) {
        m0 = fmaxf(m0, fmaxf(zz[nt][0], zz[nt][1]));
        m1 = fmaxf(m1, fmaxf(zz[nt][2], zz[nt][3]));
    }
    m0 = fmaxf(m0, __shfl_xor_sync(0xffffffffu, m0, 1));
    m0 = fmaxf(m0, __shfl_xor_sync(0xffffffffu, m0, 2));
    m1 = fmaxf(m1, __shfl_xor_sync(0xffffffffu, m1, 1));
    m1 = fmaxf(m1, __shfl_xor_sync(0xffffffffu, m1, 2));
    float s0 = 0.0f, s1 = 0.0f;
#pragma unroll
    for (int nt = 0; nt < 5; ++nt) {
        s0 += __expf(zz[nt][0] - m0) + __expf(zz[nt][1] - m0);
        s1 += __expf(zz[nt][2] - m1) + __expf(zz[nt][3] - m1);
    }
    s0 += __shfl_xor_sync(0xffffffffu, s0, 1);
    s0 += __shfl_xor_sync(0xffffffffu, s0, 2);
    s1 += __shfl_xor_sync(0xffffffffu, s1, 1);
    s1 += __shfl_xor_sync(0xffffffffu, s1, 2);
    float lse0 = m0 + logf(s0);
    float lse1 = m1 + logf(s1);

    int r0 = row0 + wid * 16 + g;
    int r1 = r0 + 8;
#pragma unroll
    for (int nt = 0; nt < 5; ++nt) {
        int col = nt * 8 + 2 * tq;
        if (r0 < n)
            *(float2*)(out + (size_t)r0 * C + col) =
                make_float2(zz[nt][0] - lse0, zz[nt][1] - lse0);
        if (r1 < n)
            *(float2*)(out + (size_t)r1 * C + col) =
                make_float2(zz[nt][2] - lse1, zz[nt][3] - lse1);
    }

    // tail: re-zero prep state for the next call/replay (grid = 391*256 >= 2n? no:
    // 100096 threads cover gt < n for cnt AND degc separately below)
    int gt = blockIdx.x * blockDim.x + threadIdx.x;
    if (gt < n) { g_cnt[gt] = 0; g_degc[gt] = 0; }
    if (gt < NB) { g_bflag[gt] = 0; g_bagg[gt] = 0; }
}

static void* sym_addr(const void* sym) {
    void* p = nullptr;
    cudaGetSymbolAddress(&p, sym);
    return p;
}

extern "C" void kernel_launch(void* const* d_in, const int* in_sizes, int n_in,
                              void* d_out, int out_size) {
    const float* x  = (const float*)d_in[0];
    const int*   ei = (const int*)d_in[1];
    const float* W1 = (const float*)d_in[2];
    const float* b1 = (const float*)d_in[3];
    const float* W2 = (const float*)d_in[4];
    const float* b2 = (const float*)d_in[5];
    float*       out = (float*)d_out;

    int N = in_sizes[0] / D;
    int E = in_sizes[1] / 2;
    int n4 = N * D / 4;

    __half* x16  = (__half*)sym_addr((const void*)g_x16_);
    __half* tx1h = (__half*)sym_addr((const void*)g_tx1h_);
    __half* tx2h = (__half*)sym_addr((const void*)g_tx2h_);
    __half* hh   = (__half*)sym_addr((const void*)g_hh_);

    dim3 b256(256);
    int gE  = (E + 255) / 256;
    int gN4 = (n4 + 255) / 256;
    int gSp = (N * 32 + 255) / 256;
    int gG  = (N + 127) / 128;
    int nb  = (N + 1023) / 1024;

    // side stream for the independent convert kernel (kernel_launch runs only a
    // few times — correctness + capture — so per-call creation is fine; graph
    // replays reuse the captured nodes, not this host code)
    cudaStream_t s2;
    cudaEvent_t evF, evJ;
    cudaStreamCreateWithFlags(&s2, cudaStreamNonBlocking);
    cudaEventCreateWithFlags(&evF, cudaEventDisableTiming);
    cudaEventCreateWithFlags(&evJ, cudaEventDisableTiming);

    // fork: conv runs concurrently with the CSR-build chain
    cudaEventRecord(evF, 0);
    cudaStreamWaitEvent(s2, evF, 0);
    k_conv<<<gN4, b256, 0, s2>>>(x, W1, W2, n4);
    cudaEventRecord(evJ, s2);

    // CSR build chain (main stream); state was zeroed by the previous call's tail
    k_count<<<gE, b256>>>(ei, E);
    k_scanf<<<nb, b256>>>(N, nb);
    k_scatter<<<gE, b256>>>(ei, E);

    // join before SpMV (needs x16 from conv)
    cudaStreamWaitEvent(0, evJ, 0);

    // layer 1
    k_spmv_h<<<gSp, b256>>>(x16,  tx1h, nullptr, 1.0f, N);
    k_spmv_h<<<gSp, b256>>>(tx1h, tx2h, x16,     2.0f, N);
    k_gemm1h<<<gG, b256>>>(b1, N);

    // layer 2 (k_gemm2 tail re-zeroes prep state for the next call/replay)
    k_spmv_h<<<gSp, b256>>>(hh,   tx1h, nullptr, 1.0f, N);
    k_spmv_h<<<gSp, b256>>>(tx1h, tx2h, hh,      2.0f, N);
    k_gemm2<<<gG, b256>>>(b2, out, N);
}

// round 15
// speedup vs baseline: 1.0852x; 1.0204x over previous
#include <cuda_runtime.h>
#include <cuda_fp16.h>
#include <math.h>
#include <stdint.h>

#define MAX_N 50000
#define MAX_E 800000
#define D 128
#define C 40
#define ELLW 96

// ---------------- static scratch ----------------
// g_degc / g_elc are zero at module load and re-zeroed at the END of every
// kernel_launch (tail of k_gemm2), so each call sees them zeroed.
__device__ int   g_degc[MAX_N];          // src-degree histogram
__device__ int   g_elc[MAX_N];           // ELL per-node fill counters (= in-degree)
__device__ int   g_ell[MAX_N * ELLW];    // ELL: src node ids, row stride ELLW
__device__ float g_dinv[MAX_N];          // deg^{-1/2}
__device__ float g_rs[MAX_N];            // deg^{+1/2} (0 if deg==0)
// fp16 feature buffers (uint4 for 16B alignment)
__device__ uint4 g_x16_[MAX_N * D / 8];  // true x
__device__ uint4 g_xs_[MAX_N * D / 8];   // scaled x~ = dinv*x
__device__ uint4 g_t1_[MAX_N * D / 8];   // scaled T~1 (layer 1 and layer 2 reuse)
__device__ uint4 g_t2_[MAX_N * D / 8];   // true Tx2 / T2'
__device__ uint4 g_hh_[MAX_N * D / 8];   // scaled h~ = dinv*relu(...)
// W^T fp16: w1t [128n][384k], w2t [40n][384k]
__device__ uint4 g_w1t_[128 * 384 / 8];
__device__ uint4 g_w2t_[40 * 384 / 8];

// ---------------- fused histogram + ELL build (one pass over edges) ----------------
__global__ void k_ell(const int* __restrict__ ei, int E) {
    int e = blockIdx.x * blockDim.x + threadIdx.x;
    if (e < E) {
        int s = ei[e];
        int t = ei[E + e];
        atomicAdd(&g_degc[s], 1);
        int p = atomicAdd(&g_elc[t], 1);
        g_ell[(size_t)t * ELLW + p] = s;
    }
}

// ---------------- dinv / rs / scaled-x (no scan needed) ----------------
__global__ void k_dinvx(const float* __restrict__ x, int n, int n4) {
    int i = blockIdx.x * blockDim.x + threadIdx.x;
    if (i < n4) {
        int row = i >> 5;                  // 32 float4 per 128-wide row
        int d = g_degc[row];
        float sc = (d > 0) ? rsqrtf((float)d) : 0.0f;
        float4 v = ((const float4*)x)[i];
        __half2 h0 = __floats2half2_rn(v.x * sc, v.y * sc);
        __half2 h1 = __floats2half2_rn(v.z * sc, v.w * sc);
        uint2 o;
        o.x = *(uint32_t*)&h0;
        o.y = *(uint32_t*)&h1;
        *(uint2*)((__half*)g_xs_ + (size_t)i * 4) = o;
    }
    if (i < n) {
        int d = g_degc[i];
        g_dinv[i] = (d > 0) ? rsqrtf((float)d) : 0.0f;
        g_rs[i]   = (d > 0) ? sqrtf((float)d)  : 0.0f;
    }
}

// ---------------- convert: x->fp16(true), W1^T, W2^T (side stream) ----------------
__global__ void k_conv(const float* __restrict__ x, const float* __restrict__ W1,
                       const float* __restrict__ W2, int n4) {
    int i = blockIdx.x * blockDim.x + threadIdx.x;
    if (i < n4) {
        float4 v = ((const float4*)x)[i];
        __half2 h0 = __floats2half2_rn(v.x, v.y);
        __half2 h1 = __floats2half2_rn(v.z, v.w);
        uint2 o;
        o.x = *(uint32_t*)&h0;
        o.y = *(uint32_t*)&h1;
        *(uint2*)((__half*)g_x16_ + (size_t)i * 4) = o;
    }
    if (i < 128 * 384) {
        int n = i / 384;
        int r = i % 384;
        int term = r >> 7;
        int k = r & 127;
        ((__half*)g_w1t_)[i] = __float2half(W1[(size_t)term * D * D + (size_t)k * D + n]);
    }
    if (i < C * 384) {
        int n = i / 384;
        int r = i % 384;
        int term = r >> 7;
        int k = r & 127;
        ((__half*)g_w2t_)[i] = __float2half(W2[(size_t)term * D * C + (size_t)k * C + n]);
    }
}

// ---------------- SpMV: ELL gather, weight-free inner loop ----------------
// mode 0: out = -dinv[t]^2 * acc                      (store SCALED, no sub)
// mode 1: out = -2*dinv[t]*acc - sub[t]               (sub true; store TRUE)
// mode 2: out = -2*dinv[t]*acc - rs[t]*sub[t]         (sub scaled; store TRUE)
__global__ void k_spmv(const __half* __restrict__ hin, __half* __restrict__ hout,
                       const __half* __restrict__ sub, int mode, int n) {
    int node = blockIdx.x * (blockDim.x >> 5) + (threadIdx.x >> 5);
    int lane = threadIdx.x & 31;
    int half = lane >> 4;
    int hl = lane & 15;
    if (node >= n) return;
    int cnt = g_elc[node];
    const int* lst = g_ell + (size_t)node * ELLW;
    float acc[8];
#pragma unroll
    for (int q = 0; q < 8; ++q) acc[q] = 0.0f;

    for (int j = 0; j < cnt; j += 2) {
        int jj = j + half;
        if (jj < cnt) {
            int s = __ldg(&lst[jj]);
            uint4 u = *(const uint4*)(hin + (size_t)s * D + hl * 8);
            float2 f0 = __half22float2(*(__half2*)&u.x);
            float2 f1 = __half22float2(*(__half2*)&u.y);
            float2 f2 = __half22float2(*(__half2*)&u.z);
            float2 f3 = __half22float2(*(__half2*)&u.w);
            acc[0] += f0.x; acc[1] += f0.y;
            acc[2] += f1.x; acc[3] += f1.y;
            acc[4] += f2.x; acc[5] += f2.y;
            acc[6] += f3.x; acc[7] += f3.y;
        }
    }
#pragma unroll
    for (int q = 0; q < 8; ++q)
        acc[q] += __shfl_xor_sync(0xffffffffu, acc[q], 16);

    if (half == 0) {
        float dv = g_dinv[node];
        float coef = (mode == 0) ? (-dv * dv) : (-2.0f * dv);
        float r[8];
#pragma unroll
        for (int q = 0; q < 8; ++q) r[q] = coef * acc[q];
        if (mode != 0) {
            float ss = (mode == 2) ? g_rs[node] : 1.0f;
            uint4 u = *(const uint4*)(sub + (size_t)node * D + hl * 8);
            float2 f0 = __half22float2(*(__half2*)&u.x);
            float2 f1 = __half22float2(*(__half2*)&u.y);
            float2 f2 = __half22float2(*(__half2*)&u.z);
            float2 f3 = __half22float2(*(__half2*)&u.w);
            r[0] -= ss * f0.x; r[1] -= ss * f0.y;
            r[2] -= ss * f1.x; r[3] -= ss * f1.y;
            r[4] -= ss * f2.x; r[5] -= ss * f2.y;
            r[6] -= ss * f3.x; r[7] -= ss * f3.y;
        }
        __half2 h0 = __floats2half2_rn(r[0], r[1]);
        __half2 h1 = __floats2half2_rn(r[2], r[3]);
        __half2 h2 = __floats2half2_rn(r[4], r[5]);
        __half2 h3 = __floats2half2_rn(r[6], r[7]);
        uint4 o;
        o.x = *(uint32_t*)&h0; o.y = *(uint32_t*)&h1;
        o.z = *(uint32_t*)&h2; o.w = *(uint32_t*)&h3;
        *(uint4*)(hout + (size_t)node * D + hl * 8) = o;
    }
}

// fp32-exact scale of 8 packed halves
__device__ __forceinline__ uint4 scale8h(uint4 v, float sc) {
    uint4 o;
    uint32_t* vi = (uint32_t*)&v;
    uint32_t* oi = (uint32_t*)&o;
#pragma unroll
    for (int q = 0; q < 4; ++q) {
        float2 f = __half22float2(*(__half2*)&vi[q]);
        __half2 h = __floats2half2_rn(f.x * sc, f.y * sc);
        oi[q] = *(uint32_t*)&h;
    }
    return o;
}

// ---------------- layer-1 GEMM: fp16 mma ----------------
// A terms: 0 = x16 (true), 1 = T~1 (scale by rs[row]), 2 = Tx2 (true)
// Output: h~ = dinv[row] * relu(z + b1)
#define S1 40

__global__ void k_gemm1h(const float* __restrict__ b1, int n) {
    __shared__ __half As1[128 * S1];
    __shared__ __half Bs1[128 * S1];
    __shared__ float bsh[128];

    int tid = threadIdx.x;
    int wid = tid >> 5, lane = tid & 31;
    int wm = wid >> 1;
    int wn = wid & 1;
    int g = lane >> 2, tq = lane & 3;
    int row0 = blockIdx.x * 128;

    if (tid < 128) bsh[tid] = b1[tid];

    __half* hh = (__half*)g_hh_;
    const __half* w1t = (const __half*)g_w1t_;

    float c[2][8][4];
#pragma unroll
    for (int mt = 0; mt < 2; ++mt)
#pragma unroll
        for (int nt = 0; nt < 8; ++nt)
#pragma unroll
            for (int q = 0; q < 4; ++q) c[mt][nt][q] = 0.0f;

    for (int ch = 0; ch < 12; ++ch) {
        int term = ch >> 2;
        int coff = (ch & 3) * 32;
        const __half* A = (term == 0) ? (const __half*)g_x16_
                        : (term == 1) ? (const __half*)g_t1_
                                      : (const __half*)g_t2_;
        bool doScale = (term == 1);

#pragma unroll
        for (int q = 0; q < 2; ++q) {
            int idx = tid + q * 256;
            int r = idx >> 2;
            int c8 = (idx & 3) * 8;
            int grow = row0 + r;
            uint4 v = make_uint4(0u, 0u, 0u, 0u);
            if (grow < n) {
                v = *(const uint4*)(A + (size_t)grow * D + coff + c8);
                if (doScale) v = scale8h(v, g_rs[grow]);
            }
            *(uint4*)&As1[r * S1 + c8] = v;
        }
#pragma unroll
        for (int q = 0; q < 2; ++q) {
            int idx = tid + q * 256;
            int r = idx >> 2;
            int c8 = (idx & 3) * 8;
            *(uint4*)&Bs1[r * S1 + c8] =
                *(const uint4*)(w1t + (size_t)r * 384 + term * 128 + coff + c8);
        }
        __syncthreads();

#pragma unroll
        for (int ks = 0; ks < 2; ++ks) {
            int kb = ks * 16;
            uint32_t a[2][4];
#pragma unroll
            for (int mt = 0; mt < 2; ++mt) {
                const __half* ar = &As1[(wm * 32 + mt * 16 + g) * S1 + kb + 2 * tq];
                a[mt][0] = *(const uint32_t*)ar;
                a[mt][1] = *(const uint32_t*)(ar + 8 * S1);
                a[mt][2] = *(const uint32_t*)(ar + 8);
                a[mt][3] = *(const uint32_t*)(ar + 8 * S1 + 8);
            }
#pragma unroll
            for (int nt = 0; nt < 8; ++nt) {
                const __half* br = &Bs1[(wn * 64 + nt * 8 + g) * S1 + kb + 2 * tq];
                uint32_t b0 = *(const uint32_t*)br;
                uint32_t b1r = *(const uint32_t*)(br + 8);
#pragma unroll
                for (int mt = 0; mt < 2; ++mt) {
                    asm volatile(
                        "mma.sync.aligned.m16n8k16.row.col.f32.f16.f16.f32 "
                        "{%0,%1,%2,%3}, {%4,%5,%6,%7}, {%8,%9}, {%0,%1,%2,%3};\n"
                        : "+f"(c[mt][nt][0]), "+f"(c[mt][nt][1]),
                          "+f"(c[mt][nt][2]), "+f"(c[mt][nt][3])
                        : "r"(a[mt][0]), "r"(a[mt][1]), "r"(a[mt][2]), "r"(a[mt][3]),
                          "r"(b0), "r"(b1r));
                }
            }
        }
        __syncthreads();
    }

#pragma unroll
    for (int mt = 0; mt < 2; ++mt) {
        int r0 = row0 + wm * 32 + mt * 16 + g;
        int r1 = r0 + 8;
        float dv0 = (r0 < n) ? g_dinv[r0] : 0.0f;
        float dv1 = (r1 < n) ? g_dinv[r1] : 0.0f;
#pragma unroll
        for (int nt = 0; nt < 8; ++nt) {
            int col = wn * 64 + nt * 8 + 2 * tq;
            float bb0 = bsh[col], bb1 = bsh[col + 1];
            if (r0 < n) {
                __half2 v0 = __floats2half2_rn(dv0 * fmaxf(c[mt][nt][0] + bb0, 0.f),
                                               dv0 * fmaxf(c[mt][nt][1] + bb1, 0.f));
                *(__half2*)(hh + (size_t)r0 * D + col) = v0;
            }
            if (r1 < n) {
                __half2 v1 = __floats2half2_rn(dv1 * fmaxf(c[mt][nt][2] + bb0, 0.f),
                                               dv1 * fmaxf(c[mt][nt][3] + bb1, 0.f));
                *(__half2*)(hh + (size_t)r1 * D + col) = v1;
            }
        }
    }
}

// ---------------- layer-2 GEMM + log_softmax + tail state re-zero ----------------
// A terms: 0 = h~ (scale rs), 1 = T~1' (scale rs), 2 = T2' (true)
#define S2 40

__global__ void k_gemm2(const float* __restrict__ b2, float* __restrict__ out, int n) {
    __shared__ __half As2[128 * S2];
    __shared__ __half Bs2[40 * S2];
    __shared__ float bsh[40];

    int tid = threadIdx.x;
    int wid = tid >> 5, lane = tid & 31;
    int g = lane >> 2, tq = lane & 3;
    int row0 = blockIdx.x * 128;

    if (tid < 40) bsh[tid] = b2[tid];

    const __half* w2t = (const __half*)g_w2t_;

    float c[5][4];
#pragma unroll
    for (int nt = 0; nt < 5; ++nt)
#pragma unroll
        for (int q = 0; q < 4; ++q) c[nt][q] = 0.0f;

    for (int ch = 0; ch < 12; ++ch) {
        int term = ch >> 2;
        int coff = (ch & 3) * 32;
        const __half* A = (term == 0) ? (const __half*)g_hh_
                        : (term == 1) ? (const __half*)g_t1_
                                      : (const __half*)g_t2_;
        bool doScale = (term != 2);

#pragma unroll
        for (int q = 0; q < 2; ++q) {
            int idx = tid + q * 256;
            int r = idx >> 2;
            int c8 = (idx & 3) * 8;
            int grow = row0 + r;
            uint4 v = make_uint4(0u, 0u, 0u, 0u);
            if (grow < n) {
                v = *(const uint4*)(A + (size_t)grow * D + coff + c8);
                if (doScale) v = scale8h(v, g_rs[grow]);
            }
            *(uint4*)&As2[r * S2 + c8] = v;
        }
        if (tid < 160) {
            int r = tid >> 2;
            int c8 = (tid & 3) * 8;
            *(uint4*)&Bs2[r * S2 + c8] =
                *(const uint4*)(w2t + (size_t)r * 384 + term * 128 + coff + c8);
        }
        __syncthreads();

#pragma unroll
        for (int ks = 0; ks < 2; ++ks) {
            int kb = ks * 16;
            const __half* ar = &As2[(wid * 16 + g) * S2 + kb + 2 * tq];
            uint32_t a0 = *(const uint32_t*)ar;
            uint32_t a1 = *(const uint32_t*)(ar + 8 * S2);
            uint32_t a2 = *(const uint32_t*)(ar + 8);
            uint32_t a3 = *(const uint32_t*)(ar + 8 * S2 + 8);
#pragma unroll
            for (int nt = 0; nt < 5; ++nt) {
                const __half* br = &Bs2[(nt * 8 + g) * S2 + kb + 2 * tq];
                uint32_t b0 = *(const uint32_t*)br;
                uint32_t b1r = *(const uint32_t*)(br + 8);
                asm volatile(
                    "mma.sync.aligned.m16n8k16.row.col.f32.f16.f16.f32 "
                    "{%0,%1,%2,%3}, {%4,%5,%6,%7}, {%8,%9}, {%0,%1,%2,%3};\n"
                    : "+f"(c[nt][0]), "+f"(c[nt][1]), "+f"(c[nt][2]), "+f"(c[nt][3])
                    : "r"(a0), "r"(a1), "r"(a2), "r"(a3), "r"(b0), "r"(b1r));
            }
        }
        __syncthreads();
    }

    float zz[5][4];
#pragma unroll
    for (int nt = 0; nt < 5; ++nt) {
        float bb0 = bsh[nt * 8 + 2 * tq];
        float bb1 = bsh[nt * 8 + 2 * tq + 1];
        zz[nt][0] = c[nt][0] + bb0;
        zz[nt][1] = c[nt][1] + bb1;
        zz[nt][2] = c[nt][2] + bb0;
        zz[nt][3] = c[nt][3] + bb1;
    }
    float m0 = -INFINITY, m1 = -INFINITY;
#pragma unroll
    for (int nt = 0; nt < 5; ++nt) {
        m0 = fmaxf(m0, fmaxf(zz[nt][0], zz[nt][1]));
        m1 = fmaxf(m1, fmaxf(zz[nt][2], zz[nt][3]));
    }
    m0 = fmaxf(m0, __shfl_xor_sync(0xffffffffu, m0, 1));
    m0 = fmaxf(m0, __shfl_xor_sync(0xffffffffu, m0, 2));
    m1 = fmaxf(m1, __shfl_xor_sync(0xffffffffu, m1, 1));
    m1 = fmaxf(m1, __shfl_xor_sync(0xffffffffu, m1, 2));
    float s0 = 0.0f, s1 = 0.0f;
#pragma unroll
    for (int nt = 0; nt < 5; ++nt) {
        s0 += __expf(zz[nt][0] - m0) + __expf(zz[nt][1] - m0);
        s1 += __expf(zz[nt][2] - m1) + __expf(zz[nt][3] - m1);
    }
    s0 += __shfl_xor_sync(0xffffffffu, s0, 1);
    s0 += __shfl_xor_sync(0xffffffffu, s0, 2);
    s1 += __shfl_xor_sync(0xffffffffu, s1, 1);
    s1 += __shfl_xor_sync(0xffffffffu, s1, 2);
    float lse0 = m0 + logf(s0);
    float lse1 = m1 + logf(s1);

    int r0 = row0 + wid * 16 + g;
    int r1 = r0 + 8;
#pragma unroll
    for (int nt = 0; nt < 5; ++nt) {
        int col = nt * 8 + 2 * tq;
        if (r0 < n)
            *(float2*)(out + (size_t)r0 * C + col) =
                make_float2(zz[nt][0] - lse0, zz[nt][1] - lse0);
        if (r1 < n)
            *(float2*)(out + (size_t)r1 * C + col) =
                make_float2(zz[nt][2] - lse1, zz[nt][3] - lse1);
    }

    // tail: re-zero prep state for the next call/replay
    int gt = blockIdx.x * blockDim.x + threadIdx.x;
    if (gt < n) { g_degc[gt] = 0; g_elc[gt] = 0; }
}

static void* sym_addr(const void* sym) {
    void* p = nullptr;
    cudaGetSymbolAddress(&p, sym);
    return p;
}

extern "C" void kernel_launch(void* const* d_in, const int* in_sizes, int n_in,
                              void* d_out, int out_size) {
    const float* x  = (const float*)d_in[0];
    const int*   ei = (const int*)d_in[1];
    const float* W1 = (const float*)d_in[2];
    const float* b1 = (const float*)d_in[3];
    const float* W2 = (const float*)d_in[4];
    const float* b2 = (const float*)d_in[5];
    float*       out = (float*)d_out;

    int N = in_sizes[0] / D;
    int E = in_sizes[1] / 2;
    int n4 = N * D / 4;

    __half* x16 = (__half*)sym_addr((const void*)g_x16_);
    __half* xs  = (__half*)sym_addr((const void*)g_xs_);
    __half* t1  = (__half*)sym_addr((const void*)g_t1_);
    __half* t2  = (__half*)sym_addr((const void*)g_t2_);
    __half* hh  = (__half*)sym_addr((const void*)g_hh_);

    dim3 b256(256);
    int gE  = (E + 255) / 256;
    int gN4 = (n4 + 255) / 256;
    int gSp = (N * 32 + 255) / 256;
    int gG  = (N + 127) / 128;

    // side stream: independent conversions overlap the ELL build
    cudaStream_t s2;
    cudaEvent_t evF, evJ;
    cudaStreamCreateWithFlags(&s2, cudaStreamNonBlocking);
    cudaEventCreateWithFlags(&evF, cudaEventDisableTiming);
    cudaEventCreateWithFlags(&evJ, cudaEventDisableTiming);

    cudaEventRecord(evF, 0);
    cudaStreamWaitEvent(s2, evF, 0);
    k_conv<<<gN4, b256, 0, s2>>>(x, W1, W2, n4);
    cudaEventRecord(evJ, s2);

    // main: fused histogram+ELL, then dinv/rs/x~ (no scan)
    k_ell<<<gE, b256>>>(ei, E);
    k_dinvx<<<gN4, b256>>>(x, N, n4);

    // layer 1: T~1 = scaled L x ; Tx2 = 2 L Tx1 - x (true)
    k_spmv<<<gSp, b256>>>(xs, t1, nullptr, 0, N);
    cudaStreamWaitEvent(0, evJ, 0);   // join: spmv2 needs x16, gemm1 needs w1t
    k_spmv<<<gSp, b256>>>(t1, t2, x16, 1, N);
    k_gemm1h<<<gG, b256>>>(b1, N);

    // layer 2: T~1' = scaled L h ; T2' = 2 L T1' - h (true)
    k_spmv<<<gSp, b256>>>(hh, t1, nullptr, 0, N);
    k_spmv<<<gSp, b256>>>(t1, t2, hh, 2, N);
    k_gemm2<<<gG, b256>>>(b2, out, N);
}

// round 16
// speedup vs baseline: 1.1619x; 1.0706x over previous
#include <cuda_runtime.h>
#include <cuda_fp16.h>
#include <math.h>
#include <stdint.h>

#define MAX_N 50000
#define MAX_E 800000
#define D 128
#define C 40
#define ELLW 96

// ---------------- static scratch ----------------
// g_degc / g_elc are zero at module load and re-zeroed at the END of every
// kernel_launch (tail of k_gemm2), so each call sees them zeroed.
__device__ int   g_degc[MAX_N];          // src-degree histogram
__device__ int   g_elc[MAX_N];           // ELL per-node fill counters (= in-degree)
__device__ int   g_ell[MAX_N * ELLW];    // ELL: src node ids, row stride ELLW
__device__ float g_dinv[MAX_N];          // deg^{-1/2}
__device__ float g_rs[MAX_N];            // deg^{+1/2} (0 if deg==0)
// fp16 feature buffers (uint4 for 16B alignment)
__device__ uint4 g_x16_[MAX_N * D / 8];  // true x
__device__ uint4 g_xs_[MAX_N * D / 8];   // scaled x~ = dinv*x
__device__ uint4 g_t1_[MAX_N * D / 8];   // scaled T~1
__device__ uint4 g_t2_[MAX_N * D / 8];   // true Tx2 / T2'
__device__ uint4 g_hh_[MAX_N * D / 8];   // scaled h~ = dinv*relu(...)
// W^T fp16: w1t [128n][384k], w2t [40n][384k]
__device__ uint4 g_w1t_[128 * 384 / 8];
__device__ uint4 g_w2t_[40 * 384 / 8];

// ---------------- fused histogram + ELL build ----------------
__global__ void k_ell(const int* __restrict__ ei, int E) {
    int e = blockIdx.x * blockDim.x + threadIdx.x;
    if (e < E) {
        int s = ei[e];
        int t = ei[E + e];
        atomicAdd(&g_degc[s], 1);
        int p = atomicAdd(&g_elc[t], 1);
        g_ell[(size_t)t * ELLW + p] = s;
    }
}

// ---------------- dinv / rs / scaled-x ----------------
__global__ void k_dinvx(const float* __restrict__ x, int n, int n4) {
    int i = blockIdx.x * blockDim.x + threadIdx.x;
    if (i < n4) {
        int row = i >> 5;
        int d = g_degc[row];
        float sc = (d > 0) ? rsqrtf((float)d) : 0.0f;
        float4 v = ((const float4*)x)[i];
        __half2 h0 = __floats2half2_rn(v.x * sc, v.y * sc);
        __half2 h1 = __floats2half2_rn(v.z * sc, v.w * sc);
        uint2 o;
        o.x = *(uint32_t*)&h0;
        o.y = *(uint32_t*)&h1;
        *(uint2*)((__half*)g_xs_ + (size_t)i * 4) = o;
    }
    if (i < n) {
        int d = g_degc[i];
        g_dinv[i] = (d > 0) ? rsqrtf((float)d) : 0.0f;
        g_rs[i]   = (d > 0) ? sqrtf((float)d)  : 0.0f;
    }
}

// ---------------- convert: x->fp16(true), W1^T, W2^T (side stream) ----------------
__global__ void k_conv(const float* __restrict__ x, const float* __restrict__ W1,
                       const float* __restrict__ W2, int n4) {
    int i = blockIdx.x * blockDim.x + threadIdx.x;
    if (i < n4) {
        float4 v = ((const float4*)x)[i];
        __half2 h0 = __floats2half2_rn(v.x, v.y);
        __half2 h1 = __floats2half2_rn(v.z, v.w);
        uint2 o;
        o.x = *(uint32_t*)&h0;
        o.y = *(uint32_t*)&h1;
        *(uint2*)((__half*)g_x16_ + (size_t)i * 4) = o;
    }
    if (i < 128 * 384) {
        int n = i / 384;
        int r = i % 384;
        int term = r >> 7;
        int k = r & 127;
        ((__half*)g_w1t_)[i] = __float2half(W1[(size_t)term * D * D + (size_t)k * D + n]);
    }
    if (i < C * 384) {
        int n = i / 384;
        int r = i % 384;
        int term = r >> 7;
        int k = r & 127;
        ((__half*)g_w2t_)[i] = __float2half(W2[(size_t)term * D * C + (size_t)k * C + n]);
    }
}

// ---------------- SpMV: ELL gather, fp16 pair pre-combine ----------------
// Each warp-half processes 2 edges/iter (stride 4); pairs are HADD2-combined in
// fp16, then converted once and accumulated in fp32.
// mode 0: out = -dinv[t]^2 * acc                      (store SCALED, no sub)
// mode 1: out = -2*dinv[t]*acc - sub[t]               (sub true; store TRUE)
// mode 2: out = -2*dinv[t]*acc - rs[t]*sub[t]         (sub scaled; store TRUE)
__global__ void k_spmv(const __half* __restrict__ hin, __half* __restrict__ hout,
                       const __half* __restrict__ sub, int mode, int n) {
    int node = blockIdx.x * (blockDim.x >> 5) + (threadIdx.x >> 5);
    int lane = threadIdx.x & 31;
    int half = lane >> 4;
    int hl = lane & 15;
    if (node >= n) return;
    int cnt = g_elc[node];
    const int* lst = g_ell + (size_t)node * ELLW;
    float acc[8];
#pragma unroll
    for (int q = 0; q < 8; ++q) acc[q] = 0.0f;

    for (int j = 0; j < cnt; j += 4) {
        int ja = j + half;        // half 0: j     ; half 1: j+1
        int jb = ja + 2;          // half 0: j+2   ; half 1: j+3
        uint4 ua = make_uint4(0u, 0u, 0u, 0u);
        uint4 ub = make_uint4(0u, 0u, 0u, 0u);
        if (ja < cnt) {
            int s = __ldg(&lst[ja]);
            ua = *(const uint4*)(hin + (size_t)s * D + hl * 8);
        }
        if (jb < cnt) {
            int s = __ldg(&lst[jb]);
            ub = *(const uint4*)(hin + (size_t)s * D + hl * 8);
        }
        // fp16 pair pre-combine (one rounding per pair, non-accumulating)
        __half2 s0 = __hadd2(*(__half2*)&ua.x, *(__half2*)&ub.x);
        __half2 s1 = __hadd2(*(__half2*)&ua.y, *(__half2*)&ub.y);
        __half2 s2 = __hadd2(*(__half2*)&ua.z, *(__half2*)&ub.z);
        __half2 s3 = __hadd2(*(__half2*)&ua.w, *(__half2*)&ub.w);
        float2 f0 = __half22float2(s0);
        float2 f1 = __half22float2(s1);
        float2 f2 = __half22float2(s2);
        float2 f3 = __half22float2(s3);
        acc[0] += f0.x; acc[1] += f0.y;
        acc[2] += f1.x; acc[3] += f1.y;
        acc[4] += f2.x; acc[5] += f2.y;
        acc[6] += f3.x; acc[7] += f3.y;
    }
#pragma unroll
    for (int q = 0; q < 8; ++q)
        acc[q] += __shfl_xor_sync(0xffffffffu, acc[q], 16);

    if (half == 0) {
        float dv = g_dinv[node];
        float coef = (mode == 0) ? (-dv * dv) : (-2.0f * dv);
        float r[8];
#pragma unroll
        for (int q = 0; q < 8; ++q) r[q] = coef * acc[q];
        if (mode != 0) {
            float ss = (mode == 2) ? g_rs[node] : 1.0f;
            uint4 u = *(const uint4*)(sub + (size_t)node * D + hl * 8);
            float2 f0 = __half22float2(*(__half2*)&u.x);
            float2 f1 = __half22float2(*(__half2*)&u.y);
            float2 f2 = __half22float2(*(__half2*)&u.z);
            float2 f3 = __half22float2(*(__half2*)&u.w);
            r[0] -= ss * f0.x; r[1] -= ss * f0.y;
            r[2] -= ss * f1.x; r[3] -= ss * f1.y;
            r[4] -= ss * f2.x; r[5] -= ss * f2.y;
            r[6] -= ss * f3.x; r[7] -= ss * f3.y;
        }
        __half2 h0 = __floats2half2_rn(r[0], r[1]);
        __half2 h1 = __floats2half2_rn(r[2], r[3]);
        __half2 h2 = __floats2half2_rn(r[4], r[5]);
        __half2 h3 = __floats2half2_rn(r[6], r[7]);
        uint4 o;
        o.x = *(uint32_t*)&h0; o.y = *(uint32_t*)&h1;
        o.z = *(uint32_t*)&h2; o.w = *(uint32_t*)&h3;
        *(uint4*)(hout + (size_t)node * D + hl * 8) = o;
    }
}

// fp32-exact scale of 8 packed halves
__device__ __forceinline__ uint4 scale8h(uint4 v, float sc) {
    uint4 o;
    uint32_t* vi = (uint32_t*)&v;
    uint32_t* oi = (uint32_t*)&o;
#pragma unroll
    for (int q = 0; q < 4; ++q) {
        float2 f = __half22float2(*(__half2*)&vi[q]);
        __half2 h = __floats2half2_rn(f.x * sc, f.y * sc);
        oi[q] = *(uint32_t*)&h;
    }
    return o;
}

// ---------------- layer-1 GEMM: fp16 mma ----------------
#define S1 40

__global__ void k_gemm1h(const float* __restrict__ b1, int n) {
    __shared__ __half As1[128 * S1];
    __shared__ __half Bs1[128 * S1];
    __shared__ float bsh[128];

    int tid = threadIdx.x;
    int wid = tid >> 5, lane = tid & 31;
    int wm = wid >> 1;
    int wn = wid & 1;
    int g = lane >> 2, tq = lane & 3;
    int row0 = blockIdx.x * 128;

    if (tid < 128) bsh[tid] = b1[tid];

    __half* hh = (__half*)g_hh_;
    const __half* w1t = (const __half*)g_w1t_;

    float c[2][8][4];
#pragma unroll
    for (int mt = 0; mt < 2; ++mt)
#pragma unroll
        for (int nt = 0; nt < 8; ++nt)
#pragma unroll
            for (int q = 0; q < 4; ++q) c[mt][nt][q] = 0.0f;

    for (int ch = 0; ch < 12; ++ch) {
        int term = ch >> 2;
        int coff = (ch & 3) * 32;
        const __half* A = (term == 0) ? (const __half*)g_x16_
                        : (term == 1) ? (const __half*)g_t1_
                                      : (const __half*)g_t2_;
        bool doScale = (term == 1);

#pragma unroll
        for (int q = 0; q < 2; ++q) {
            int idx = tid + q * 256;
            int r = idx >> 2;
            int c8 = (idx & 3) * 8;
            int grow = row0 + r;
            uint4 v = make_uint4(0u, 0u, 0u, 0u);
            if (grow < n) {
                v = *(const uint4*)(A + (size_t)grow * D + coff + c8);
                if (doScale) v = scale8h(v, g_rs[grow]);
            }
            *(uint4*)&As1[r * S1 + c8] = v;
        }
#pragma unroll
        for (int q = 0; q < 2; ++q) {
            int idx = tid + q * 256;
            int r = idx >> 2;
            int c8 = (idx & 3) * 8;
            *(uint4*)&Bs1[r * S1 + c8] =
                *(const uint4*)(w1t + (size_t)r * 384 + term * 128 + coff + c8);
        }
        __syncthreads();

#pragma unroll
        for (int ks = 0; ks < 2; ++ks) {
            int kb = ks * 16;
            uint32_t a[2][4];
#pragma unroll
            for (int mt = 0; mt < 2; ++mt) {
                const __half* ar = &As1[(wm * 32 + mt * 16 + g) * S1 + kb + 2 * tq];
                a[mt][0] = *(const uint32_t*)ar;
                a[mt][1] = *(const uint32_t*)(ar + 8 * S1);
                a[mt][2] = *(const uint32_t*)(ar + 8);
                a[mt][3] = *(const uint32_t*)(ar + 8 * S1 + 8);
            }
#pragma unroll
            for (int nt = 0; nt < 8; ++nt) {
                const __half* br = &Bs1[(wn * 64 + nt * 8 + g) * S1 + kb + 2 * tq];
                uint32_t b0 = *(const uint32_t*)br;
                uint32_t b1r = *(const uint32_t*)(br + 8);
#pragma unroll
                for (int mt = 0; mt < 2; ++mt) {
                    asm volatile(
                        "mma.sync.aligned.m16n8k16.row.col.f32.f16.f16.f32 "
                        "{%0,%1,%2,%3}, {%4,%5,%6,%7}, {%8,%9}, {%0,%1,%2,%3};\n"
                        : "+f"(c[mt][nt][0]), "+f"(c[mt][nt][1]),
                          "+f"(c[mt][nt][2]), "+f"(c[mt][nt][3])
                        : "r"(a[mt][0]), "r"(a[mt][1]), "r"(a[mt][2]), "r"(a[mt][3]),
                          "r"(b0), "r"(b1r));
                }
            }
        }
        __syncthreads();
    }

#pragma unroll
    for (int mt = 0; mt < 2; ++mt) {
        int r0 = row0 + wm * 32 + mt * 16 + g;
        int r1 = r0 + 8;
        float dv0 = (r0 < n) ? g_dinv[r0] : 0.0f;
        float dv1 = (r1 < n) ? g_dinv[r1] : 0.0f;
#pragma unroll
        for (int nt = 0; nt < 8; ++nt) {
            int col = wn * 64 + nt * 8 + 2 * tq;
            float bb0 = bsh[col], bb1 = bsh[col + 1];
            if (r0 < n) {
                __half2 v0 = __floats2half2_rn(dv0 * fmaxf(c[mt][nt][0] + bb0, 0.f),
                                               dv0 * fmaxf(c[mt][nt][1] + bb1, 0.f));
                *(__half2*)(hh + (size_t)r0 * D + col) = v0;
            }
            if (r1 < n) {
                __half2 v1 = __floats2half2_rn(dv1 * fmaxf(c[mt][nt][2] + bb0, 0.f),
                                               dv1 * fmaxf(c[mt][nt][3] + bb1, 0.f));
                *(__half2*)(hh + (size_t)r1 * D + col) = v1;
            }
        }
    }
}

// ---------------- layer-2 GEMM + log_softmax + tail state re-zero ----------------
#define S2 40

__global__ void k_gemm2(const float* __restrict__ b2, float* __restrict__ out, int n) {
    __shared__ __half As2[128 * S2];
    __shared__ __half Bs2[40 * S2];
    __shared__ float bsh[40];

    int tid = threadIdx.x;
    int wid = tid >> 5, lane = tid & 31;
    int g = lane >> 2, tq = lane & 3;
    int row0 = blockIdx.x * 128;

    if (tid < 40) bsh[tid] = b2[tid];

    const __half* w2t = (const __half*)g_w2t_;

    float c[5][4];
#pragma unroll
    for (int nt = 0; nt < 5; ++nt)
#pragma unroll
        for (int q = 0; q < 4; ++q) c[nt][q] = 0.0f;

    for (int ch = 0; ch < 12; ++ch) {
        int term = ch >> 2;
        int coff = (ch & 3) * 32;
        const __half* A = (term == 0) ? (const __half*)g_hh_
                        : (term == 1) ? (const __half*)g_t1_
                                      : (const __half*)g_t2_;
        bool doScale = (term != 2);

#pragma unroll
        for (int q = 0; q < 2; ++q) {
            int idx = tid + q * 256;
            int r = idx >> 2;
            int c8 = (idx & 3) * 8;
            int grow = row0 + r;
            uint4 v = make_uint4(0u, 0u, 0u, 0u);
            if (grow < n) {
                v = *(const uint4*)(A + (size_t)grow * D + coff + c8);
                if (doScale) v = scale8h(v, g_rs[grow]);
            }
            *(uint4*)&As2[r * S2 + c8] = v;
        }
        if (tid < 160) {
            int r = tid >> 2;
            int c8 = (tid & 3) * 8;
            *(uint4*)&Bs2[r * S2 + c8] =
                *(const uint4*)(w2t + (size_t)r * 384 + term * 128 + coff + c8);
        }
        __syncthreads();

#pragma unroll
        for (int ks = 0; ks < 2; ++ks) {
            int kb = ks * 16;
            const __half* ar = &As2[(wid * 16 + g) * S2 + kb + 2 * tq];
            uint32_t a0 = *(const uint32_t*)ar;
            uint32_t a1 = *(const uint32_t*)(ar + 8 * S2);
            uint32_t a2 = *(const uint32_t*)(ar + 8);
            uint32_t a3 = *(const uint32_t*)(ar + 8 * S2 + 8);
#pragma unroll
            for (int nt = 0; nt < 5; ++nt) {
                const __half* br = &Bs2[(nt * 8 + g) * S2 + kb + 2 * tq];
                uint32_t b0 = *(const uint32_t*)br;
                uint32_t b1r = *(const uint32_t*)(br + 8);
                asm volatile(
                    "mma.sync.aligned.m16n8k16.row.col.f32.f16.f16.f32 "
                    "{%0,%1,%2,%3}, {%4,%5,%6,%7}, {%8,%9}, {%0,%1,%2,%3};\n"
                    : "+f"(c[nt][0]), "+f"(c[nt][1]), "+f"(c[nt][2]), "+f"(c[nt][3])
                    : "r"(a0), "r"(a1), "r"(a2), "r"(a3), "r"(b0), "r"(b1r));
            }
        }
        __syncthreads();
    }

    float zz[5][4];
#pragma unroll
    for (int nt = 0; nt < 5; ++nt) {
        float bb0 = bsh[nt * 8 + 2 * tq];
        float bb1 = bsh[nt * 8 + 2 * tq + 1];
        zz[nt][0] = c[nt][0] + bb0;
        zz[nt][1] = c[nt][1] + bb1;
        zz[nt][2] = c[nt][2] + bb0;
        zz[nt][3] = c[nt][3] + bb1;
    }
    float m0 = -INFINITY, m1 = -INFINITY;
#pragma unroll
    for (int nt = 0; nt < 5; ++nt) {
        m0 = fmaxf(m0, fmaxf(zz[nt][0], zz[nt][1]));
        m1 = fmaxf(m1, fmaxf(zz[nt][2], zz[nt][3]));
    }
    m0 = fmaxf(m0, __shfl_xor_sync(0xffffffffu, m0, 1));
    m0 = fmaxf(m0, __shfl_xor_sync(0xffffffffu, m0, 2));
    m1 = fmaxf(m1, __shfl_xor_sync(0xffffffffu, m1, 1));
    m1 = fmaxf(m1, __shfl_xor_sync(0xffffffffu, m1, 2));
    float s0 = 0.0f, s1 = 0.0f;
#pragma unroll
    for (int nt = 0; nt < 5; ++nt) {
        s0 += __expf(zz[nt][0] - m0) + __expf(zz[nt][1] - m0);
        s1 += __expf(zz[nt][2] - m1) + __expf(zz[nt][3] - m1);
    }
    s0 += __shfl_xor_sync(0xffffffffu, s0, 1);
    s0 += __shfl_xor_sync(0xffffffffu, s0, 2);
    s1 += __shfl_xor_sync(0xffffffffu, s1, 1);
    s1 += __shfl_xor_sync(0xffffffffu, s1, 2);
    float lse0 = m0 + logf(s0);
    float lse1 = m1 + logf(s1);

    int r0 = row0 + wid * 16 + g;
    int r1 = r0 + 8;
#pragma unroll
    for (int nt = 0; nt < 5; ++nt) {
        int col = nt * 8 + 2 * tq;
        if (r0 < n)
            *(float2*)(out + (size_t)r0 * C + col) =
                make_float2(zz[nt][0] - lse0, zz[nt][1] - lse0);
        if (r1 < n)
            *(float2*)(out + (size_t)r1 * C + col) =
                make_float2(zz[nt][2] - lse1, zz[nt][3] - lse1);
    }

    // tail: re-zero prep state for the next call/replay
    int gt = blockIdx.x * blockDim.x + threadIdx.x;
    if (gt < n) { g_degc[gt] = 0; g_elc[gt] = 0; }
}

static void* sym_addr(const void* sym) {
    void* p = nullptr;
    cudaGetSymbolAddress(&p, sym);
    return p;
}

extern "C" void kernel_launch(void* const* d_in, const int* in_sizes, int n_in,
                              void* d_out, int out_size) {
    const float* x  = (const float*)d_in[0];
    const int*   ei = (const int*)d_in[1];
    const float* W1 = (const float*)d_in[2];
    const float* b1 = (const float*)d_in[3];
    const float* W2 = (const float*)d_in[4];
    const float* b2 = (const float*)d_in[5];
    float*       out = (float*)d_out;

    int N = in_sizes[0] / D;
    int E = in_sizes[1] / 2;
    int n4 = N * D / 4;

    __half* x16 = (__half*)sym_addr((const void*)g_x16_);
    __half* xs  = (__half*)sym_addr((const void*)g_xs_);
    __half* t1  = (__half*)sym_addr((const void*)g_t1_);
    __half* t2  = (__half*)sym_addr((const void*)g_t2_);
    __half* hh  = (__half*)sym_addr((const void*)g_hh_);

    dim3 b256(256);
    int gE  = (E + 255) / 256;
    int gN4 = (n4 + 255) / 256;
    int gSp = (N * 32 + 255) / 256;
    int gG  = (N + 127) / 128;

    // side stream: independent conversions overlap the ELL build
    cudaStream_t s2;
    cudaEvent_t evF, evJ;
    cudaStreamCreateWithFlags(&s2, cudaStreamNonBlocking);
    cudaEventCreateWithFlags(&evF, cudaEventDisableTiming);
    cudaEventCreateWithFlags(&evJ, cudaEventDisableTiming);

    cudaEventRecord(evF, 0);
    cudaStreamWaitEvent(s2, evF, 0);
    k_conv<<<gN4, b256, 0, s2>>>(x, W1, W2, n4);
    cudaEventRecord(evJ, s2);

    // main: fused histogram+ELL, then dinv/rs/x~ (no scan)
    k_ell<<<gE, b256>>>(ei, E);
    k_dinvx<<<gN4, b256>>>(x, N, n4);

    // layer 1: T~1 = scaled L x ; Tx2 = 2 L Tx1 - x (true)
    k_spmv<<<gSp, b256>>>(xs, t1, nullptr, 0, N);
    cudaStreamWaitEvent(0, evJ, 0);   // join: spmv2 needs x16, gemm1 needs w1t
    k_spmv<<<gSp, b256>>>(t1, t2, x16, 1, N);
    k_gemm1h<<<gG, b256>>>(b1, N);

    // layer 2: T~1' = scaled L h ; T2' = 2 L T1' - h (true)
    k_spmv<<<gSp, b256>>>(hh, t1, nullptr, 0, N);
    k_spmv<<<gSp, b256>>>(t1, t2, hh, 2, N);
    k_gemm2<<<gG, b256>>>(b2, out, N);
}